// round 10
// baseline (speedup 1.0000x reference)
#include <cuda_runtime.h>
#include <cuda_bf16.h>
#include <cstdint>

static constexpr int D = 128;       // feature dim == hidden dim
static constexpr int MAXN = 100000;

// accumulator: neighbor sums ((1+eps)*x folded into MLP A-load)
__device__ __align__(128) float g_acc[(size_t)MAXN * D];
// pre-split, transposed bf16 weights: [n][k] row-major, 128x128 each
__device__ __align__(16) __nv_bfloat16 g_w1hi[16384];
__device__ __align__(16) __nv_bfloat16 g_w1lo[16384];
__device__ __align__(16) __nv_bfloat16 g_w2hi[16384];
__device__ __align__(16) __nv_bfloat16 g_w2lo[16384];

// ---------------------------------------------------------------------------
// helpers
// ---------------------------------------------------------------------------
__device__ __forceinline__ uint32_t smem_to_u32(const void* p) {
    uint32_t a;
    asm("{ .reg .u64 t; cvta.to.shared.u64 t, %1; cvt.u32.u64 %0, t; }"
        : "=r"(a) : "l"(p));
    return a;
}
__device__ __forceinline__ void ldsm4(uint32_t r[4], uint32_t addr) {
    asm volatile("ldmatrix.sync.aligned.m8n8.x4.shared.b16 {%0,%1,%2,%3}, [%4];"
                 : "=r"(r[0]), "=r"(r[1]), "=r"(r[2]), "=r"(r[3]) : "r"(addr));
}
__device__ __forceinline__ void mma16816(float c[4], const uint32_t a[4],
                                         uint32_t b0, uint32_t b1) {
    asm volatile("mma.sync.aligned.m16n8k16.row.col.f32.bf16.bf16.f32 "
                 "{%0,%1,%2,%3}, {%4,%5,%6,%7}, {%8,%9}, {%0,%1,%2,%3};"
                 : "+f"(c[0]), "+f"(c[1]), "+f"(c[2]), "+f"(c[3])
                 : "r"(a[0]), "r"(a[1]), "r"(a[2]), "r"(a[3]),
                   "r"(b0), "r"(b1));
}
__device__ __forceinline__ void split2(float v0, float v1,
                                       uint32_t& hp, uint32_t& lp) {
    __nv_bfloat16 h0 = __float2bfloat16(v0);
    __nv_bfloat16 h1 = __float2bfloat16(v1);
    __nv_bfloat16 l0 = __float2bfloat16(v0 - __bfloat162float(h0));
    __nv_bfloat16 l1 = __float2bfloat16(v1 - __bfloat162float(h1));
    hp = (uint32_t)__bfloat16_as_ushort(h0) |
         ((uint32_t)__bfloat16_as_ushort(h1) << 16);
    lp = (uint32_t)__bfloat16_as_ushort(l0) |
         ((uint32_t)__bfloat16_as_ushort(l1) << 16);
}
// 256-bit global load with L2 cache-hint policy
__device__ __forceinline__ void ldg_v8(float r[8], const float* p, uint64_t pol) {
    uint32_t t0, t1, t2, t3, t4, t5, t6, t7;
    asm volatile("ld.global.nc.L2::cache_hint.v8.b32 "
                 "{%0,%1,%2,%3,%4,%5,%6,%7}, [%8], %9;"
                 : "=r"(t0), "=r"(t1), "=r"(t2), "=r"(t3),
                   "=r"(t4), "=r"(t5), "=r"(t6), "=r"(t7)
                 : "l"(p), "l"(pol));
    r[0] = __uint_as_float(t0); r[1] = __uint_as_float(t1);
    r[2] = __uint_as_float(t2); r[3] = __uint_as_float(t3);
    r[4] = __uint_as_float(t4); r[5] = __uint_as_float(t5);
    r[6] = __uint_as_float(t6); r[7] = __uint_as_float(t7);
}
// 128-bit vector reduction with evict_last policy on the destination
__device__ __forceinline__ void red_v4(float* p, float m0, float m1,
                                       float m2, float m3, uint64_t pol) {
    asm volatile("red.global.add.L2::cache_hint.v4.f32 [%0], {%1,%2,%3,%4}, %5;"
                 :: "l"(p), "f"(m0), "f"(m1), "f"(m2), "f"(m3), "l"(pol)
                 : "memory");
}

// ---------------------------------------------------------------------------
// setup: blocks [0,128) split weights; blocks [128,...) zero g_acc
// ---------------------------------------------------------------------------
__global__ void setup_kernel(const float* __restrict__ W1,
                             const float* __restrict__ W2, int nzero4) {
    int b = blockIdx.x, t = threadIdx.x;
    if (b < 128) {
        int idx = b * 256 + t;           // 0..32767
        int m = idx >> 14;
        int r = idx & 16383;
        int k = r >> 7, n = r & 127;
        float w = (m ? W2 : W1)[k * 128 + n];
        __nv_bfloat16 h = __float2bfloat16(w);
        __nv_bfloat16 l = __float2bfloat16(w - __bfloat162float(h));
        int e = n * 128 + k;
        if (m) { g_w2hi[e] = h; g_w2lo[e] = l; }
        else   { g_w1hi[e] = h; g_w1lo[e] = l; }
    } else {
        int i = (b - 128) * 256 + t;
        if (i < nzero4)
            reinterpret_cast<float4*>(g_acc)[i] = make_float4(0.f, 0.f, 0.f, 0.f);
    }
}

// ---------------------------------------------------------------------------
// scatter: 16 lanes per edge (each lane owns 8 floats = 32 B).
// v8 loads (halves LDG transactions); 2x red.v4 per endpoint per lane,
// destination pinned evict_last (acc rows re-touched ~deg times).
// ---------------------------------------------------------------------------
__global__ void scatter_kernel(const float* __restrict__ x,
                               const float* __restrict__ ea,
                               const int* __restrict__ ei, int E) {
    int gtid = blockIdx.x * blockDim.x + threadIdx.x;
    int e = gtid >> 4;
    int sub = gtid & 15;
    if (e >= E) return;

    uint64_t polL, polF;
    asm("createpolicy.fractional.L2::evict_last.b64 %0, 1.0;" : "=l"(polL));
    asm("createpolicy.fractional.L2::evict_first.b64 %0, 1.0;" : "=l"(polF));

    int u = ei[e];
    int v = ei[E + e];
    int off = sub * 8;

    float a[8], xu[8], xv[8];
    ldg_v8(a,  ea + (size_t)e * D + off, polF);
    ldg_v8(xu, x + (size_t)u * D + off, polL);
    ldg_v8(xv, x + (size_t)v * D + off, polL);

    float mu[8], mv[8];
    #pragma unroll
    for (int i = 0; i < 8; i++) {
        mu[i] = fmaxf(xv[i] + a[i], 0.0f);
        mv[i] = fmaxf(xu[i] + a[i], 0.0f);
    }
    float* pu = g_acc + (size_t)u * D + off;
    float* pv = g_acc + (size_t)v * D + off;
    red_v4(pu,     mu[0], mu[1], mu[2], mu[3], polL);
    red_v4(pu + 4, mu[4], mu[5], mu[6], mu[7], polL);
    red_v4(pv,     mv[0], mv[1], mv[2], mv[3], polL);
    red_v4(pv + 4, mv[4], mv[5], mv[6], mv[7], polL);
}

// ---------------------------------------------------------------------------
// fused MLP on HMMA (bf16 2-term split => ~fp32 accuracy)
// CTA: 256 threads / 8 warps / 128 rows; warp owns rows [16w,16w+16).
// A fragments built directly from gmem (no A smem). Hidden kept in regs.
// smem: W hi/lo [128][136] only => 2 CTAs/SM.
// ---------------------------------------------------------------------------
static constexpr int RS = 136;                       // row stride (bf16)
static constexpr int SM_WHI = 0;
static constexpr int SM_WLO = SM_WHI + 128 * RS * 2; // 34816
static constexpr int SM_B1  = SM_WLO + 128 * RS * 2; // 69632
static constexpr int SM_B2  = SM_B1 + 512;
static constexpr int SM_TOTAL = SM_B2 + 512;         // 70656 B

__device__ __forceinline__ void copy_w(char* smem, int dst,
                                       const __nv_bfloat16* src, int tid) {
    const uint4* s = reinterpret_cast<const uint4*>(src);
    #pragma unroll
    for (int i = tid; i < 2048; i += 256) {
        int r = i >> 4, c8 = i & 15;
        *reinterpret_cast<uint4*>(smem + dst + (r * RS + c8 * 8) * 2) = s[i];
    }
}

__device__ __forceinline__ void load_split(const float* ap, const float* xp,
                                           bool valid, int k, float s,
                                           uint32_t& hp, uint32_t& lp) {
    float v0 = 0.f, v1 = 0.f;
    if (valid) {
        float2 pa = *reinterpret_cast<const float2*>(ap + k);
        float2 px = *reinterpret_cast<const float2*>(xp + k);
        v0 = fmaf(s, px.x, pa.x);
        v1 = fmaf(s, px.y, pa.y);
    }
    split2(v0, v1, hp, lp);
}

__global__ void __launch_bounds__(256, 2)
mlp_kernel(const float* __restrict__ x, const float* __restrict__ eps,
           const float* __restrict__ b1, const float* __restrict__ b2,
           float* __restrict__ out, int N) {
    extern __shared__ char smem[];
    uint32_t sb = smem_to_u32(smem);
    int tid = threadIdx.x;
    int wid = tid >> 5;
    int lane = tid & 31;
    int row0 = blockIdx.x * 128;

    copy_w(smem, SM_WHI, g_w1hi, tid);
    copy_w(smem, SM_WLO, g_w1lo, tid);
    if (tid < 128) {
        reinterpret_cast<float*>(smem + SM_B1)[tid] = b1[tid];
        reinterpret_cast<float*>(smem + SM_B2)[tid] = b2[tid];
    }
    __syncthreads();

    int m2 = (lane & 3) * 2;
    int g  = lane >> 2;
    int r0 = row0 + wid * 16 + g;
    int r1 = r0 + 8;
    bool val0 = r0 < N, val1 = r1 < N;
    const float* a0p = g_acc + (size_t)r0 * D;
    const float* a1p = g_acc + (size_t)r1 * D;
    const float* x0p = x + (size_t)r0 * D;
    const float* x1p = x + (size_t)r1 * D;
    float s = 1.0f + eps[0];

    int brow = (lane & 7) + ((lane & 16) ? 8 : 0);
    int bcol = (lane & 8) ? 8 : 0;

    float c1[16][4];
    #pragma unroll
    for (int i = 0; i < 16; i++)
        c1[i][0] = c1[i][1] = c1[i][2] = c1[i][3] = 0.f;

    // ---- layer 1: A from gmem, W1 from smem ----
    #pragma unroll 2
    for (int kk = 0; kk < 8; kk++) {
        int k0 = kk * 16 + m2;
        uint32_t ahi[4], alo[4];
        load_split(a0p, x0p, val0, k0,     s, ahi[0], alo[0]);
        load_split(a1p, x1p, val1, k0,     s, ahi[1], alo[1]);
        load_split(a0p, x0p, val0, k0 + 8, s, ahi[2], alo[2]);
        load_split(a1p, x1p, val1, k0 + 8, s, ahi[3], alo[3]);
        #pragma unroll
        for (int nt2 = 0; nt2 < 8; nt2++) {
            uint32_t bAddr = sb + SM_WHI +
                (uint32_t)((nt2 * 16 + brow) * RS + kk * 16 + bcol) * 2;
            uint32_t bhi[4], blo[4];
            ldsm4(bhi, bAddr);
            ldsm4(blo, bAddr + (SM_WLO - SM_WHI));
            mma16816(c1[2 * nt2],     ahi, bhi[0], bhi[1]);
            mma16816(c1[2 * nt2],     ahi, blo[0], blo[1]);
            mma16816(c1[2 * nt2],     alo, bhi[0], bhi[1]);
            mma16816(c1[2 * nt2 + 1], ahi, bhi[2], bhi[3]);
            mma16816(c1[2 * nt2 + 1], ahi, blo[2], blo[3]);
            mma16816(c1[2 * nt2 + 1], alo, bhi[2], bhi[3]);
        }
    }

    // ---- hidden = relu(c1 + b1), re-fragmented in registers ----
    const float* b1s = reinterpret_cast<const float*>(smem + SM_B1);
    uint32_t hh[8][4], hl[8][4];
    #pragma unroll
    for (int j = 0; j < 8; j++) {
        float be0 = b1s[16 * j + m2],     be1 = b1s[16 * j + m2 + 1];
        float bo0 = b1s[16 * j + 8 + m2], bo1 = b1s[16 * j + 8 + m2 + 1];
        split2(fmaxf(c1[2 * j][0] + be0, 0.f),
               fmaxf(c1[2 * j][1] + be1, 0.f), hh[j][0], hl[j][0]);
        split2(fmaxf(c1[2 * j][2] + be0, 0.f),
               fmaxf(c1[2 * j][3] + be1, 0.f), hh[j][1], hl[j][1]);
        split2(fmaxf(c1[2 * j + 1][0] + bo0, 0.f),
               fmaxf(c1[2 * j + 1][1] + bo1, 0.f), hh[j][2], hl[j][2]);
        split2(fmaxf(c1[2 * j + 1][2] + bo0, 0.f),
               fmaxf(c1[2 * j + 1][3] + bo1, 0.f), hh[j][3], hl[j][3]);
    }

    __syncthreads();               // everyone done reading W1
    copy_w(smem, SM_WHI, g_w2hi, tid);
    copy_w(smem, SM_WLO, g_w2lo, tid);
    __syncthreads();

    // ---- layer 2 in two n-halves (c2 = 32 regs) ----
    const float* b2s = reinterpret_cast<const float*>(smem + SM_B2);
    #pragma unroll
    for (int h = 0; h < 2; h++) {
        float c2[8][4];
        #pragma unroll
        for (int i = 0; i < 8; i++)
            c2[i][0] = c2[i][1] = c2[i][2] = c2[i][3] = 0.f;

        #pragma unroll
        for (int kk = 0; kk < 8; kk++) {
            #pragma unroll
            for (int i = 0; i < 4; i++) {
                int nt2 = h * 4 + i;
                uint32_t bAddr = sb + SM_WHI +
                    (uint32_t)((nt2 * 16 + brow) * RS + kk * 16 + bcol) * 2;
                uint32_t bhi[4], blo[4];
                ldsm4(bhi, bAddr);
                ldsm4(blo, bAddr + (SM_WLO - SM_WHI));
                mma16816(c2[2 * i],     hh[kk], bhi[0], bhi[1]);
                mma16816(c2[2 * i],     hh[kk], blo[0], blo[1]);
                mma16816(c2[2 * i],     hl[kk], bhi[0], bhi[1]);
                mma16816(c2[2 * i + 1], hh[kk], bhi[2], bhi[3]);
                mma16816(c2[2 * i + 1], hh[kk], blo[2], blo[3]);
                mma16816(c2[2 * i + 1], hl[kk], bhi[2], bhi[3]);
            }
        }

        #pragma unroll
        for (int nt = 0; nt < 8; nt++) {
            int col = (h * 8 + nt) * 8 + m2;
            float bb0 = b2s[col], bb1 = b2s[col + 1];
            if (val0)
                *reinterpret_cast<float2*>(out + (size_t)r0 * D + col) =
                    make_float2(c2[nt][0] + bb0, c2[nt][1] + bb1);
            if (val1)
                *reinterpret_cast<float2*>(out + (size_t)r1 * D + col) =
                    make_float2(c2[nt][2] + bb0, c2[nt][3] + bb1);
        }
    }
}

// ---------------------------------------------------------------------------
// launch: setup (prep + zero) -> scatter -> HMMA MLP   (3 launches total)
// ---------------------------------------------------------------------------
extern "C" void kernel_launch(void* const* d_in, const int* in_sizes, int n_in,
                              void* d_out, int out_size) {
    const float* x   = (const float*)d_in[0];
    const float* ea  = (const float*)d_in[1];
    const float* W1  = (const float*)d_in[2];
    const float* b1  = (const float*)d_in[3];
    const float* W2  = (const float*)d_in[4];
    const float* b2  = (const float*)d_in[5];
    const float* eps = (const float*)d_in[6];
    const int*   ei  = (const int*)d_in[7];

    int N = in_sizes[0] / D;
    int E = in_sizes[1] / D;

    int nzero4 = N * D / 4;
    int setup_blocks = 128 + (nzero4 + 255) / 256;
    setup_kernel<<<setup_blocks, 256>>>(W1, W2, nzero4);

    long long scatter_threads = (long long)E * 16;
    scatter_kernel<<<(int)((scatter_threads + 255) / 256), 256>>>(x, ea, ei, E);

    cudaFuncSetAttribute(mlp_kernel,
                         cudaFuncAttributeMaxDynamicSharedMemorySize, SM_TOTAL);
    int nbm = (N + 127) / 128;
    mlp_kernel<<<nbm, 256, SM_TOTAL>>>(x, eps, b1, b2, (float*)d_out, N);
}

// round 11
// speedup vs baseline: 1.3146x; 1.3146x over previous
#include <cuda_runtime.h>
#include <cuda_bf16.h>
#include <cstdint>

static constexpr int D = 128;       // feature dim == hidden dim
static constexpr int MAXN = 100000;

// accumulator: initialized to (1+eps)*x, then scatter adds messages
__device__ __align__(128) float g_acc[(size_t)MAXN * D];
// pre-split, transposed bf16 weights: [n][k] row-major, 128x128 each
__device__ __align__(16) __nv_bfloat16 g_w1hi[16384];
__device__ __align__(16) __nv_bfloat16 g_w1lo[16384];
__device__ __align__(16) __nv_bfloat16 g_w2hi[16384];
__device__ __align__(16) __nv_bfloat16 g_w2lo[16384];

// ---------------------------------------------------------------------------
// helpers
// ---------------------------------------------------------------------------
__device__ __forceinline__ uint32_t smem_to_u32(const void* p) {
    uint32_t a;
    asm("{ .reg .u64 t; cvta.to.shared.u64 t, %1; cvt.u32.u64 %0, t; }"
        : "=r"(a) : "l"(p));
    return a;
}
__device__ __forceinline__ void ldsm4(uint32_t r[4], uint32_t addr) {
    asm volatile("ldmatrix.sync.aligned.m8n8.x4.shared.b16 {%0,%1,%2,%3}, [%4];"
                 : "=r"(r[0]), "=r"(r[1]), "=r"(r[2]), "=r"(r[3]) : "r"(addr));
}
__device__ __forceinline__ void mma16816(float c[4], const uint32_t a[4],
                                         uint32_t b0, uint32_t b1) {
    asm volatile("mma.sync.aligned.m16n8k16.row.col.f32.bf16.bf16.f32 "
                 "{%0,%1,%2,%3}, {%4,%5,%6,%7}, {%8,%9}, {%0,%1,%2,%3};"
                 : "+f"(c[0]), "+f"(c[1]), "+f"(c[2]), "+f"(c[3])
                 : "r"(a[0]), "r"(a[1]), "r"(a[2]), "r"(a[3]),
                   "r"(b0), "r"(b1));
}
__device__ __forceinline__ void split2(float v0, float v1,
                                       uint32_t& hp, uint32_t& lp) {
    __nv_bfloat16 h0 = __float2bfloat16(v0);
    __nv_bfloat16 h1 = __float2bfloat16(v1);
    __nv_bfloat16 l0 = __float2bfloat16(v0 - __bfloat162float(h0));
    __nv_bfloat16 l1 = __float2bfloat16(v1 - __bfloat162float(h1));
    hp = (uint32_t)__bfloat16_as_ushort(h0) |
         ((uint32_t)__bfloat16_as_ushort(h1) << 16);
    lp = (uint32_t)__bfloat16_as_ushort(l0) |
         ((uint32_t)__bfloat16_as_ushort(l1) << 16);
}
// x row load pinned in L2 via cache-hint policy (evict_last) — R8-proven
__device__ __forceinline__ float4 ldg_keep(const float4* p, uint64_t pol) {
    float4 v;
    asm volatile("ld.global.nc.L2::cache_hint.v4.f32 {%0,%1,%2,%3}, [%4], %5;"
                 : "=f"(v.x), "=f"(v.y), "=f"(v.z), "=f"(v.w)
                 : "l"(p), "l"(pol));
    return v;
}

// ---------------------------------------------------------------------------
// setup: blocks [0,128) split weights; blocks [128,...) acc = (1+eps)*x
// ---------------------------------------------------------------------------
__global__ void setup_kernel(const float* __restrict__ W1,
                             const float* __restrict__ W2,
                             const float* __restrict__ x,
                             const float* __restrict__ eps, int ninit4) {
    int b = blockIdx.x, t = threadIdx.x;
    if (b < 128) {
        int idx = b * 256 + t;           // 0..32767
        int m = idx >> 14;
        int r = idx & 16383;
        int k = r >> 7, n = r & 127;
        float w = (m ? W2 : W1)[k * 128 + n];
        __nv_bfloat16 h = __float2bfloat16(w);
        __nv_bfloat16 l = __float2bfloat16(w - __bfloat162float(h));
        int e = n * 128 + k;
        if (m) { g_w2hi[e] = h; g_w2lo[e] = l; }
        else   { g_w1hi[e] = h; g_w1lo[e] = l; }
    } else {
        int i = (b - 128) * 256 + t;
        if (i < ninit4) {
            float s = 1.0f + *eps;
            float4 v = reinterpret_cast<const float4*>(x)[i];
            v.x *= s; v.y *= s; v.z *= s; v.w *= s;
            reinterpret_cast<float4*>(g_acc)[i] = v;
        }
    }
}

// ---------------------------------------------------------------------------
// scatter (exact R8 form, 211 us proven): one warp per edge, red.v4 into
// g_acc; x pinned evict_last, ea streamed evict-first
// ---------------------------------------------------------------------------
__global__ void scatter_kernel(const float* __restrict__ x,
                               const float* __restrict__ ea,
                               const int* __restrict__ ei, int E) {
    int gtid = blockIdx.x * blockDim.x + threadIdx.x;
    int e = gtid >> 5;
    int lane = gtid & 31;
    if (e >= E) return;

    uint64_t pol;
    asm volatile("createpolicy.fractional.L2::evict_last.b64 %0, 1.0;"
                 : "=l"(pol));

    int u = ei[e];
    int v = ei[E + e];

    float4 a  = __ldcs(reinterpret_cast<const float4*>(ea + (size_t)e * D) + lane);
    float4 xu = ldg_keep(reinterpret_cast<const float4*>(x + (size_t)u * D) + lane, pol);
    float4 xv = ldg_keep(reinterpret_cast<const float4*>(x + (size_t)v * D) + lane, pol);

    float4 mu, mv;
    mu.x = fmaxf(xv.x + a.x, 0.0f); mu.y = fmaxf(xv.y + a.y, 0.0f);
    mu.z = fmaxf(xv.z + a.z, 0.0f); mu.w = fmaxf(xv.w + a.w, 0.0f);
    mv.x = fmaxf(xu.x + a.x, 0.0f); mv.y = fmaxf(xu.y + a.y, 0.0f);
    mv.z = fmaxf(xu.z + a.z, 0.0f); mv.w = fmaxf(xu.w + a.w, 0.0f);

    float* pu = g_acc + (size_t)u * D + lane * 4;
    float* pv = g_acc + (size_t)v * D + lane * 4;
    asm volatile("red.global.add.v4.f32 [%0], {%1,%2,%3,%4};"
                 :: "l"(pu), "f"(mu.x), "f"(mu.y), "f"(mu.z), "f"(mu.w) : "memory");
    asm volatile("red.global.add.v4.f32 [%0], {%1,%2,%3,%4};"
                 :: "l"(pv), "f"(mv.x), "f"(mv.y), "f"(mv.z), "f"(mv.w) : "memory");
}

// ---------------------------------------------------------------------------
// PERSISTENT fused MLP on HMMA (bf16 2-term split => ~fp32 accuracy)
// 512 threads / 16 warps per CTA; W1+W2 hi/lo staged in smem ONCE;
// grid-stride loop over 256-row tiles; NO syncs after the initial barrier.
// ---------------------------------------------------------------------------
static constexpr int RS = 136;                        // row stride (bf16)
static constexpr int WT = 128 * RS * 2;               // 34816 B per tile
static constexpr int SM_W1HI = 0;
static constexpr int SM_W1LO = SM_W1HI + WT;
static constexpr int SM_W2HI = SM_W1LO + WT;
static constexpr int SM_W2LO = SM_W2HI + WT;          // 139264
static constexpr int SM_B1   = SM_W2LO + WT;
static constexpr int SM_B2   = SM_B1 + 512;
static constexpr int SM_TOTAL = SM_B2 + 512;          // 140800 B

__device__ __forceinline__ void copy_w512(char* smem, int dst,
                                          const __nv_bfloat16* src, int tid) {
    const uint4* s = reinterpret_cast<const uint4*>(src);
    #pragma unroll
    for (int i = tid; i < 2048; i += 512) {
        int r = i >> 4, c8 = i & 15;
        *reinterpret_cast<uint4*>(smem + dst + (r * RS + c8 * 8) * 2) = s[i];
    }
}

__device__ __forceinline__ void load_split(const float* ap, bool valid, int k,
                                           uint32_t& hp, uint32_t& lp) {
    float v0 = 0.f, v1 = 0.f;
    if (valid) {
        float2 p = *reinterpret_cast<const float2*>(ap + k);
        v0 = p.x; v1 = p.y;
    }
    split2(v0, v1, hp, lp);
}

__global__ void __launch_bounds__(512, 1)
mlp_kernel(const float* __restrict__ b1, const float* __restrict__ b2,
           float* __restrict__ out, int N, int ntiles) {
    extern __shared__ char smem[];
    uint32_t sb = smem_to_u32(smem);
    int tid = threadIdx.x;
    int wid = tid >> 5;
    int lane = tid & 31;

    copy_w512(smem, SM_W1HI, g_w1hi, tid);
    copy_w512(smem, SM_W1LO, g_w1lo, tid);
    copy_w512(smem, SM_W2HI, g_w2hi, tid);
    copy_w512(smem, SM_W2LO, g_w2lo, tid);
    if (tid < 128) {
        reinterpret_cast<float*>(smem + SM_B1)[tid] = b1[tid];
        reinterpret_cast<float*>(smem + SM_B2)[tid] = b2[tid];
    }
    __syncthreads();     // only barrier in the kernel

    int m2 = (lane & 3) * 2;
    int g  = lane >> 2;
    int brow = (lane & 7) + ((lane & 16) ? 8 : 0);
    int bcol = (lane & 8) ? 8 : 0;
    const float* b1s = reinterpret_cast<const float*>(smem + SM_B1);
    const float* b2s = reinterpret_cast<const float*>(smem + SM_B2);

    for (int tile = blockIdx.x; tile < ntiles; tile += gridDim.x) {
        int row0 = tile * 256;
        int r0 = row0 + wid * 16 + g;
        int r1 = r0 + 8;
        bool val0 = r0 < N, val1 = r1 < N;
        const float* a0p = g_acc + (size_t)r0 * D;
        const float* a1p = g_acc + (size_t)r1 * D;

        float c1[16][4];
        #pragma unroll
        for (int i = 0; i < 16; i++)
            c1[i][0] = c1[i][1] = c1[i][2] = c1[i][3] = 0.f;

        // ---- layer 1: A from gmem, W1 from smem ----
        #pragma unroll 2
        for (int kk = 0; kk < 8; kk++) {
            int k0 = kk * 16 + m2;
            uint32_t ahi[4], alo[4];
            load_split(a0p, val0, k0,     ahi[0], alo[0]);
            load_split(a1p, val1, k0,     ahi[1], alo[1]);
            load_split(a0p, val0, k0 + 8, ahi[2], alo[2]);
            load_split(a1p, val1, k0 + 8, ahi[3], alo[3]);
            #pragma unroll
            for (int nt2 = 0; nt2 < 8; nt2++) {
                uint32_t bAddr = sb + SM_W1HI +
                    (uint32_t)((nt2 * 16 + brow) * RS + kk * 16 + bcol) * 2;
                uint32_t bhi[4], blo[4];
                ldsm4(bhi, bAddr);
                ldsm4(blo, bAddr + WT);
                mma16816(c1[2 * nt2],     ahi, bhi[0], bhi[1]);
                mma16816(c1[2 * nt2],     ahi, blo[0], blo[1]);
                mma16816(c1[2 * nt2],     alo, bhi[0], bhi[1]);
                mma16816(c1[2 * nt2 + 1], ahi, bhi[2], bhi[3]);
                mma16816(c1[2 * nt2 + 1], ahi, blo[2], blo[3]);
                mma16816(c1[2 * nt2 + 1], alo, bhi[2], bhi[3]);
            }
        }

        // ---- hidden = relu(c1 + b1), re-fragmented in registers ----
        uint32_t hh[8][4], hl[8][4];
        #pragma unroll
        for (int j = 0; j < 8; j++) {
            float be0 = b1s[16 * j + m2],     be1 = b1s[16 * j + m2 + 1];
            float bo0 = b1s[16 * j + 8 + m2], bo1 = b1s[16 * j + 8 + m2 + 1];
            split2(fmaxf(c1[2 * j][0] + be0, 0.f),
                   fmaxf(c1[2 * j][1] + be1, 0.f), hh[j][0], hl[j][0]);
            split2(fmaxf(c1[2 * j][2] + be0, 0.f),
                   fmaxf(c1[2 * j][3] + be1, 0.f), hh[j][1], hl[j][1]);
            split2(fmaxf(c1[2 * j + 1][0] + bo0, 0.f),
                   fmaxf(c1[2 * j + 1][1] + bo1, 0.f), hh[j][2], hl[j][2]);
            split2(fmaxf(c1[2 * j + 1][2] + bo0, 0.f),
                   fmaxf(c1[2 * j + 1][3] + bo1, 0.f), hh[j][3], hl[j][3]);
        }

        // ---- layer 2 in two n-halves (c2 = 32 regs), W2 from smem ----
        #pragma unroll
        for (int h = 0; h < 2; h++) {
            float c2[8][4];
            #pragma unroll
            for (int i = 0; i < 8; i++)
                c2[i][0] = c2[i][1] = c2[i][2] = c2[i][3] = 0.f;

            #pragma unroll
            for (int kk = 0; kk < 8; kk++) {
                #pragma unroll
                for (int i = 0; i < 4; i++) {
                    int nt2 = h * 4 + i;
                    uint32_t bAddr = sb + SM_W2HI +
                        (uint32_t)((nt2 * 16 + brow) * RS + kk * 16 + bcol) * 2;
                    uint32_t bhi[4], blo[4];
                    ldsm4(bhi, bAddr);
                    ldsm4(blo, bAddr + WT);
                    mma16816(c2[2 * i],     hh[kk], bhi[0], bhi[1]);
                    mma16816(c2[2 * i],     hh[kk], blo[0], blo[1]);
                    mma16816(c2[2 * i],     hl[kk], bhi[0], bhi[1]);
                    mma16816(c2[2 * i + 1], hh[kk], bhi[2], bhi[3]);
                    mma16816(c2[2 * i + 1], hh[kk], blo[2], blo[3]);
                    mma16816(c2[2 * i + 1], hl[kk], bhi[2], bhi[3]);
                }
            }

            #pragma unroll
            for (int nt = 0; nt < 8; nt++) {
                int col = (h * 8 + nt) * 8 + m2;
                float bb0 = b2s[col], bb1 = b2s[col + 1];
                if (val0)
                    *reinterpret_cast<float2*>(out + (size_t)r0 * D + col) =
                        make_float2(c2[nt][0] + bb0, c2[nt][1] + bb1);
                if (val1)
                    *reinterpret_cast<float2*>(out + (size_t)r1 * D + col) =
                        make_float2(c2[nt][2] + bb0, c2[nt][3] + bb1);
            }
        }
    }
}

// ---------------------------------------------------------------------------
// launch: setup (prep + eps-scaled init) -> scatter -> persistent HMMA MLP
// ---------------------------------------------------------------------------
extern "C" void kernel_launch(void* const* d_in, const int* in_sizes, int n_in,
                              void* d_out, int out_size) {
    const float* x   = (const float*)d_in[0];
    const float* ea  = (const float*)d_in[1];
    const float* W1  = (const float*)d_in[2];
    const float* b1  = (const float*)d_in[3];
    const float* W2  = (const float*)d_in[4];
    const float* b2  = (const float*)d_in[5];
    const float* eps = (const float*)d_in[6];
    const int*   ei  = (const int*)d_in[7];

    int N = in_sizes[0] / D;
    int E = in_sizes[1] / D;

    int ninit4 = N * D / 4;
    int setup_blocks = 128 + (ninit4 + 255) / 256;
    setup_kernel<<<setup_blocks, 256>>>(W1, W2, x, eps, ninit4);

    long long scatter_threads = (long long)E * 32;
    scatter_kernel<<<(int)((scatter_threads + 255) / 256), 256>>>(x, ea, ei, E);

    cudaFuncSetAttribute(mlp_kernel,
                         cudaFuncAttributeMaxDynamicSharedMemorySize, SM_TOTAL);
    int ntiles = (N + 255) / 256;
    int grid = ntiles < 152 ? ntiles : 152;
    mlp_kernel<<<grid, 512, SM_TOTAL>>>(b1, b2, (float*)d_out, N, ntiles);
}